// round 5
// baseline (speedup 1.0000x reference)
#include <cuda_runtime.h>

#define N_NODES 100000
#define N_EDGES 3200000
#define D_FEAT  256
#define D_HID   30
#define HPAD    32          // h row padded to 128B so each gather is one L2 line
#define SCAN_BLOCKS 98      // ceil(100000/1024)

// ---------------- scratch (device globals; zero-initialized at load) --------
__device__ float g_h[N_NODES * HPAD];     // 12.8 MB transformed features
__device__ float g_dis[N_NODES];          // rsqrt(deg)
__device__ float g_z[N_NODES];            // per-node scalar after layer-2 transform
__device__ int   g_cnt[N_NODES];          // in-degree histogram (real edges only)
__device__ int   g_rowptr[N_NODES + 1];   // CSR row pointers (by target col)
__device__ int   g_cursor[N_NODES];       // scatter cursors
__device__ int2  g_entries[N_EDGES];      // (src_row, bits(dis[src]))
__device__ int   g_bsums[128];            // scan block sums

// ---------------- init: zero the histogram every call -----------------------
__global__ void k_init() {
    int i = blockIdx.x * 256 + threadIdx.x;
    if (i < N_NODES) g_cnt[i] = 0;
}

// ---------------- histogram of target nodes (edge_index is int32 [2,E]) -----
__global__ void k_hist(const int* __restrict__ ei) {
    int e = blockIdx.x * 256 + threadIdx.x;
    if (e < N_EDGES) {
        int c = ei[N_EDGES + e];
        if ((unsigned)c < (unsigned)N_NODES) atomicAdd(&g_cnt[c], 1);
    }
}

// ---------------- block-level exclusive scan --------------------------------
__global__ void k_scan1() {
    __shared__ int s[1024];
    int t = threadIdx.x;
    int i = blockIdx.x * 1024 + t;
    int v = (i < N_NODES) ? g_cnt[i] : 0;
    s[t] = v;
    __syncthreads();
    #pragma unroll
    for (int off = 1; off < 1024; off <<= 1) {
        int add = (t >= off) ? s[t - off] : 0;
        __syncthreads();
        s[t] += add;
        __syncthreads();
    }
    if (i < N_NODES) g_rowptr[i] = s[t] - v;   // block-local exclusive
    if (t == 1023) g_bsums[blockIdx.x] = s[t];
}

__global__ void k_scan2() {
    if (threadIdx.x == 0) {
        int acc = 0;
        for (int b = 0; b < SCAN_BLOCKS; b++) {
            int v = g_bsums[b];
            g_bsums[b] = acc;
            acc += v;
        }
    }
}

__global__ void k_scan3() {
    int i = blockIdx.x * 256 + threadIdx.x;
    if (i < N_NODES) {
        int rp = g_rowptr[i] + g_bsums[i >> 10];
        g_rowptr[i] = rp;
        g_cursor[i] = rp;
        // deg includes the self-loop (+1); deg >= 1 always
        g_dis[i] = rsqrtf((float)(g_cnt[i] + 1));
    }
    if (i == 0) g_rowptr[N_NODES] = N_EDGES;
}

// ---------------- CSR scatter: pack (src, dis[src]) -------------------------
__global__ void k_scatter(const int* __restrict__ ei) {
    int e = blockIdx.x * 256 + threadIdx.x;
    if (e < N_EDGES) {
        int r = ei[e];
        int c = ei[N_EDGES + e];
        if ((unsigned)r < (unsigned)N_NODES && (unsigned)c < (unsigned)N_NODES) {
            float dr = g_dis[r];
            int pos = atomicAdd(&g_cursor[c], 1);
            g_entries[pos] = make_int2(r, __float_as_int(dr));
        }
    }
}

// ---------------- GEMM: h = x @ W1 (fp32 FFMA) ------------------------------
// 128 threads/block, 2 nodes/thread -> 256 nodes/block. W1 staged in smem
// padded to 32 floats/row for float4 LDS; x staged in 8-wide K chunks.
__global__ void __launch_bounds__(128) k_gemm(const float* __restrict__ x,
                                              const float* __restrict__ W1) {
    __shared__ __align__(16) float Ws[D_FEAT * 32];  // 32 KB
    __shared__ float xs[256 * 9];                    // 9 KB (pad 9 vs bank conflicts)
    int t  = threadIdx.x;
    int n0 = blockIdx.x * 256;

    #pragma unroll
    for (int i = 0; i < 60; i++) {                   // 60*128 = 7680 = 256*30
        int flat = t + i * 128;
        Ws[(flat / 30) * 32 + (flat % 30)] = W1[flat];
    }

    float accA[30], accB[30];
    #pragma unroll
    for (int j = 0; j < 30; j++) { accA[j] = 0.f; accB[j] = 0.f; }

    for (int kc = 0; kc < 32; kc++) {                // 32 chunks of 8
        __syncthreads();
        #pragma unroll
        for (int i = 0; i < 4; i++) {                // 512 float4 loads / 128 thr
            int flat4 = t + i * 128;
            int n = flat4 >> 1;
            int p = flat4 & 1;
            int gn = n0 + n;
            if (gn < N_NODES) {
                float4 v = *(const float4*)&x[gn * D_FEAT + kc * 8 + p * 4];
                float* xr = &xs[n * 9 + p * 4];
                xr[0] = v.x; xr[1] = v.y; xr[2] = v.z; xr[3] = v.w;
            }
        }
        __syncthreads();
        #pragma unroll
        for (int kk = 0; kk < 8; kk++) {
            float xa = xs[t * 9 + kk];
            float xb = xs[(t + 128) * 9 + kk];
            const float* wr = &Ws[(kc * 8 + kk) * 32];
            #pragma unroll
            for (int j4 = 0; j4 < 7; j4++) {
                float4 w = *(const float4*)&wr[j4 * 4];
                accA[j4*4+0] += xa * w.x;  accB[j4*4+0] += xb * w.x;
                accA[j4*4+1] += xa * w.y;  accB[j4*4+1] += xb * w.y;
                accA[j4*4+2] += xa * w.z;  accB[j4*4+2] += xb * w.z;
                accA[j4*4+3] += xa * w.w;  accB[j4*4+3] += xb * w.w;
            }
            float2 w2 = *(const float2*)&wr[28];
            accA[28] += xa * w2.x;  accB[28] += xb * w2.x;
            accA[29] += xa * w2.y;  accB[29] += xb * w2.y;
        }
    }

    int na = n0 + t, nb = n0 + 128 + t;
    if (na < N_NODES) {
        #pragma unroll
        for (int j = 0; j < 30; j++) g_h[na * HPAD + j] = accA[j];
    }
    if (nb < N_NODES) {
        #pragma unroll
        for (int j = 0; j < 30; j++) g_h[nb * HPAD + j] = accB[j];
    }
}

// ---------------- layer-1 aggregate + relu + (·W2) fused --------------------
// One warp per target node; lanes 0..29 own features. Self-loop added
// analytically. Epilogue computes z[c] = relu(agg + b1) . W2 (never stores h1).
__global__ void __launch_bounds__(256) k_agg1(const float* __restrict__ b1,
                                              const float* __restrict__ W2) {
    int c    = blockIdx.x * 8 + (threadIdx.x >> 5);
    int lane = threadIdx.x & 31;
    float dc = g_dis[c];
    int s = g_rowptr[c];
    int e = g_rowptr[c + 1];

    // self-loop: h[c] * dis[c]^2 (pad lanes read zeros)
    float acc  = g_h[c * HPAD + lane] * (dc * dc);
    float acc2 = 0.f;

    int i = s;
    for (; i + 1 < e; i += 2) {
        int2 a = g_entries[i];
        int2 b = g_entries[i + 1];
        acc  += g_h[a.x * HPAD + lane] * (__int_as_float(a.y) * dc);
        acc2 += g_h[b.x * HPAD + lane] * (__int_as_float(b.y) * dc);
    }
    if (i < e) {
        int2 a = g_entries[i];
        acc += g_h[a.x * HPAD + lane] * (__int_as_float(a.y) * dc);
    }
    acc += acc2;

    float p = 0.f;
    if (lane < D_HID) {
        float h1 = fmaxf(acc + b1[lane], 0.f);
        p = h1 * W2[lane];
    }
    #pragma unroll
    for (int off = 16; off > 0; off >>= 1)
        p += __shfl_down_sync(0xFFFFFFFFu, p, off);
    if (lane == 0) g_z[c] = p;
}

// ---------------- layer-2 scalar aggregate + sigmoid ------------------------
// One warp per node, lanes parallel over edges (z table is L2-resident 400KB).
__global__ void __launch_bounds__(256) k_agg2(const float* __restrict__ b2,
                                              float* __restrict__ out) {
    int c    = blockIdx.x * 8 + (threadIdx.x >> 5);
    int lane = threadIdx.x & 31;
    float dc = g_dis[c];
    int s = g_rowptr[c];
    int e = g_rowptr[c + 1];

    float acc = (lane == 0) ? g_z[c] * dc * dc : 0.f;   // self-loop
    for (int i = s + lane; i < e; i += 32) {
        int2 a = g_entries[i];
        acc += g_z[a.x] * (__int_as_float(a.y) * dc);
    }
    #pragma unroll
    for (int off = 16; off > 0; off >>= 1)
        acc += __shfl_down_sync(0xFFFFFFFFu, acc, off);
    if (lane == 0) {
        float v = acc + b2[0];
        out[c] = 1.f / (1.f + __expf(-v));
    }
}

// ---------------- launcher ---------------------------------------------------
extern "C" void kernel_launch(void* const* d_in, const int* in_sizes, int n_in,
                              void* d_out, int out_size) {
    const float* x  = (const float*)d_in[0];
    const int*   ei = (const int*)d_in[1];     // int64 in source -> int32 (JAX x64 disabled)
    const float* W1 = (const float*)d_in[2];
    const float* b1 = (const float*)d_in[3];
    const float* W2 = (const float*)d_in[4];
    const float* b2 = (const float*)d_in[5];
    float*       out = (float*)d_out;

    const int nodeBlocks = (N_NODES + 255) / 256;   // 391
    const int edgeBlocks = (N_EDGES + 255) / 256;   // 12500
    const int warpBlocks = N_NODES / 8;             // 12500 (exact)

    k_init   <<<nodeBlocks, 256>>>();
    k_hist   <<<edgeBlocks, 256>>>(ei);
    k_gemm   <<<nodeBlocks, 128>>>(x, W1);
    k_scan1  <<<SCAN_BLOCKS, 1024>>>();
    k_scan2  <<<1, 32>>>();
    k_scan3  <<<nodeBlocks, 256>>>();
    k_scatter<<<edgeBlocks, 256>>>(ei);
    k_agg1   <<<warpBlocks, 256>>>(b1, W2);
    k_agg2   <<<warpBlocks, 256>>>(b2, out);
}

// round 6
// speedup vs baseline: 1.1571x; 1.1571x over previous
#include <cuda_runtime.h>

#define N_NODES 100000
#define N_EDGES 3200000
#define D_FEAT  256
#define D_HID   30
#define HPAD    32          // h row padded to 128B so each gather is one L2 line
#define SCAN_BLOCKS 98      // ceil(100000/1024)

// ---------------- scratch (device globals; zero-initialized at load) --------
__device__ float g_h[N_NODES * HPAD];     // 12.8 MB pre-scaled features h' = (xW1)*dis
__device__ float g_dis[N_NODES];          // rsqrt(deg)
__device__ float g_z[N_NODES];            // pre-scaled z' = z*dis
__device__ int   g_cnt[N_NODES];          // in-degree histogram (real edges only)
__device__ int   g_rowptr[N_NODES + 1];   // CSR row pointers (by target col)
__device__ int   g_cursor[N_NODES];       // scatter cursors
__device__ int   g_ent[N_EDGES];          // src node per CSR slot
__device__ int   g_bsums[128];            // scan block sums

// ---------------- f32x2 packed-FMA helpers (sm_100 ISA) ----------------------
__device__ __forceinline__ unsigned long long pk2(float lo, float hi) {
    unsigned long long r;
    asm("mov.b64 %0, {%1, %2};" : "=l"(r) : "f"(lo), "f"(hi));
    return r;
}
__device__ __forceinline__ void upk2(unsigned long long v, float& lo, float& hi) {
    asm("mov.b64 {%0, %1}, %2;" : "=f"(lo), "=f"(hi) : "l"(v));
}
__device__ __forceinline__ void ffma2(unsigned long long& d,
                                      unsigned long long a, unsigned long long b) {
    asm("fma.rn.f32x2 %0, %1, %2, %0;" : "+l"(d) : "l"(a), "l"(b));
}

// ---------------- init: zero the histogram every call -----------------------
__global__ void k_init() {
    int i = blockIdx.x * 256 + threadIdx.x;
    if (i < N_NODES) g_cnt[i] = 0;
}

// ---------------- histogram of target nodes (4 edges/thread, int4) ----------
__global__ void k_hist(const int* __restrict__ ei) {
    int e4 = (blockIdx.x * 256 + threadIdx.x) * 4;
    if (e4 < N_EDGES) {
        int4 v = *(const int4*)&ei[N_EDGES + e4];
        if ((unsigned)v.x < (unsigned)N_NODES) atomicAdd(&g_cnt[v.x], 1);
        if ((unsigned)v.y < (unsigned)N_NODES) atomicAdd(&g_cnt[v.y], 1);
        if ((unsigned)v.z < (unsigned)N_NODES) atomicAdd(&g_cnt[v.z], 1);
        if ((unsigned)v.w < (unsigned)N_NODES) atomicAdd(&g_cnt[v.w], 1);
    }
}

// ---------------- block-level exclusive scan --------------------------------
__global__ void k_scan1() {
    __shared__ int s[1024];
    int t = threadIdx.x;
    int i = blockIdx.x * 1024 + t;
    int v = (i < N_NODES) ? g_cnt[i] : 0;
    s[t] = v;
    __syncthreads();
    #pragma unroll
    for (int off = 1; off < 1024; off <<= 1) {
        int add = (t >= off) ? s[t - off] : 0;
        __syncthreads();
        s[t] += add;
        __syncthreads();
    }
    if (i < N_NODES) g_rowptr[i] = s[t] - v;   // block-local exclusive
    if (t == 1023) g_bsums[blockIdx.x] = s[t];
}

__global__ void k_scan2() {
    if (threadIdx.x == 0) {
        int acc = 0;
        for (int b = 0; b < SCAN_BLOCKS; b++) {
            int v = g_bsums[b];
            g_bsums[b] = acc;
            acc += v;
        }
    }
}

__global__ void k_scan3() {
    int i = blockIdx.x * 256 + threadIdx.x;
    if (i < N_NODES) {
        int rp = g_rowptr[i] + g_bsums[i >> 10];
        g_rowptr[i] = rp;
        g_cursor[i] = rp;
        g_dis[i] = rsqrtf((float)(g_cnt[i] + 1));   // deg incl. self-loop
    }
    if (i == 0) g_rowptr[N_NODES] = N_EDGES;
}

// ---------------- CSR scatter: src index only (dis folded into h') ----------
__global__ void k_scatter(const int* __restrict__ ei) {
    int e4 = (blockIdx.x * 256 + threadIdx.x) * 4;
    if (e4 < N_EDGES) {
        int4 r = *(const int4*)&ei[e4];
        int4 c = *(const int4*)&ei[N_EDGES + e4];
        if ((unsigned)r.x < (unsigned)N_NODES && (unsigned)c.x < (unsigned)N_NODES)
            g_ent[atomicAdd(&g_cursor[c.x], 1)] = r.x;
        if ((unsigned)r.y < (unsigned)N_NODES && (unsigned)c.y < (unsigned)N_NODES)
            g_ent[atomicAdd(&g_cursor[c.y], 1)] = r.y;
        if ((unsigned)r.z < (unsigned)N_NODES && (unsigned)c.z < (unsigned)N_NODES)
            g_ent[atomicAdd(&g_cursor[c.z], 1)] = r.z;
        if ((unsigned)r.w < (unsigned)N_NODES && (unsigned)c.w < (unsigned)N_NODES)
            g_ent[atomicAdd(&g_cursor[c.w], 1)] = r.w;
    }
}

// ---------------- GEMM: h' = (x @ W1) * dis  (packed f32x2 FMA) -------------
// 128 threads/block, 2 nodes/thread. Output columns packed in pairs (j, j+1)
// so W pairs load directly as b64 lanes from smem (no repacking), and the
// per-node broadcast (xa,xa) is one mov.b64 per k-step.
__global__ void __launch_bounds__(128) k_gemm(const float* __restrict__ x,
                                              const float* __restrict__ W1) {
    __shared__ __align__(16) float Ws[D_FEAT * 32];  // 32 KB, rows padded to 32
    __shared__ float xs[256 * 9];                    // pad 9 vs bank conflicts
    int t  = threadIdx.x;
    int n0 = blockIdx.x * 256;

    #pragma unroll
    for (int i = 0; i < 60; i++) {                   // 60*128 = 7680 = 256*30
        int flat = t + i * 128;
        Ws[(flat / 30) * 32 + (flat % 30)] = W1[flat];
    }

    unsigned long long accA[15], accB[15];           // (j, j+1) f32 pairs
    #pragma unroll
    for (int p = 0; p < 15; p++) { accA[p] = 0ull; accB[p] = 0ull; }

    for (int kc = 0; kc < 32; kc++) {                // 32 chunks of 8 k's
        __syncthreads();
        #pragma unroll
        for (int i = 0; i < 4; i++) {                // 512 float4 loads / 128 thr
            int flat4 = t + i * 128;
            int n = flat4 >> 1;
            int p = flat4 & 1;
            int gn = n0 + n;
            if (gn < N_NODES) {
                float4 v = *(const float4*)&x[gn * D_FEAT + kc * 8 + p * 4];
                float* xr = &xs[n * 9 + p * 4];
                xr[0] = v.x; xr[1] = v.y; xr[2] = v.z; xr[3] = v.w;
            }
        }
        __syncthreads();
        #pragma unroll
        for (int kk = 0; kk < 8; kk++) {
            unsigned long long xa2 = pk2(xs[t * 9 + kk], xs[t * 9 + kk]);
            unsigned long long xb2 = pk2(xs[(t + 128) * 9 + kk], xs[(t + 128) * 9 + kk]);
            const float* wr = &Ws[(kc * 8 + kk) * 32];
            #pragma unroll
            for (int p = 0; p < 7; p++) {            // 28 floats = 14 b64 lanes
                ulonglong2 wv = *(const ulonglong2*)(wr + p * 4);
                ffma2(accA[2 * p],     xa2, wv.x);
                ffma2(accA[2 * p + 1], xa2, wv.y);
                ffma2(accB[2 * p],     xb2, wv.x);
                ffma2(accB[2 * p + 1], xb2, wv.y);
            }
            unsigned long long wl = *(const unsigned long long*)(wr + 28);
            ffma2(accA[14], xa2, wl);
            ffma2(accB[14], xb2, wl);
        }
    }

    int na = n0 + t, nb = n0 + 128 + t;
    if (na < N_NODES) {
        float d = g_dis[na];
        #pragma unroll
        for (int p = 0; p < 15; p++) {
            float f0, f1; upk2(accA[p], f0, f1);
            g_h[na * HPAD + 2 * p]     = f0 * d;
            g_h[na * HPAD + 2 * p + 1] = f1 * d;
        }
    }
    if (nb < N_NODES) {
        float d = g_dis[nb];
        #pragma unroll
        for (int p = 0; p < 15; p++) {
            float f0, f1; upk2(accB[p], f0, f1);
            g_h[nb * HPAD + 2 * p]     = f0 * d;
            g_h[nb * HPAD + 2 * p + 1] = f1 * d;
        }
    }
}

// ---------------- layer-1 aggregate + relu + (·W2) fused --------------------
// One warp per target node; lanes 0..29 own features (30,31 read zero pad).
// Inner loop is pure gather+add (norms pre-folded). 4 accumulators for MLP.
__global__ void __launch_bounds__(256) k_agg1(const float* __restrict__ b1,
                                              const float* __restrict__ W2) {
    int c    = blockIdx.x * 8 + (threadIdx.x >> 5);
    int lane = threadIdx.x & 31;
    float dc = g_dis[c];
    int s = g_rowptr[c];
    int e = g_rowptr[c + 1];

    float a0 = g_h[c * HPAD + lane];        // self-loop term h'[c]
    float a1 = 0.f, a2 = 0.f, a3 = 0.f;

    int i = s;
    for (; i + 3 < e; i += 4) {
        int r0 = g_ent[i], r1 = g_ent[i + 1], r2 = g_ent[i + 2], r3 = g_ent[i + 3];
        a0 += g_h[r0 * HPAD + lane];
        a1 += g_h[r1 * HPAD + lane];
        a2 += g_h[r2 * HPAD + lane];
        a3 += g_h[r3 * HPAD + lane];
    }
    for (; i < e; i++)
        a0 += g_h[g_ent[i] * HPAD + lane];

    float acc = (a0 + a1) + (a2 + a3);

    float p = 0.f;
    if (lane < D_HID) {
        float h1 = fmaxf(acc * dc + b1[lane], 0.f);
        p = h1 * W2[lane];
    }
    #pragma unroll
    for (int off = 16; off > 0; off >>= 1)
        p += __shfl_down_sync(0xFFFFFFFFu, p, off);
    if (lane == 0) g_z[c] = p * dc;         // store pre-scaled z' = z*dis
}

// ---------------- layer-2 scalar aggregate + sigmoid ------------------------
__global__ void __launch_bounds__(256) k_agg2(const float* __restrict__ b2,
                                              float* __restrict__ out) {
    int c    = blockIdx.x * 8 + (threadIdx.x >> 5);
    int lane = threadIdx.x & 31;
    float dc = g_dis[c];
    int s = g_rowptr[c];
    int e = g_rowptr[c + 1];

    float acc = (lane == 0) ? g_z[c] : 0.f;             // self-loop z'[c]
    for (int i = s + lane; i < e; i += 32)
        acc += g_z[g_ent[i]];
    #pragma unroll
    for (int off = 16; off > 0; off >>= 1)
        acc += __shfl_down_sync(0xFFFFFFFFu, acc, off);
    if (lane == 0) {
        float v = acc * dc + b2[0];
        out[c] = 1.f / (1.f + __expf(-v));
    }
}

// ---------------- launcher ---------------------------------------------------
extern "C" void kernel_launch(void* const* d_in, const int* in_sizes, int n_in,
                              void* d_out, int out_size) {
    const float* x  = (const float*)d_in[0];
    const int*   ei = (const int*)d_in[1];     // int64 in source -> int32 (JAX x64 disabled)
    const float* W1 = (const float*)d_in[2];
    const float* b1 = (const float*)d_in[3];
    const float* W2 = (const float*)d_in[4];
    const float* b2 = (const float*)d_in[5];
    float*       out = (float*)d_out;

    const int nodeBlocks  = (N_NODES + 255) / 256;       // 391
    const int edge4Blocks = (N_EDGES / 4 + 255) / 256;   // 3125
    const int warpBlocks  = N_NODES / 8;                 // 12500 (exact)

    k_init   <<<nodeBlocks, 256>>>();
    k_hist   <<<edge4Blocks, 256>>>(ei);
    k_scan1  <<<SCAN_BLOCKS, 1024>>>();
    k_scan2  <<<1, 32>>>();
    k_scan3  <<<nodeBlocks, 256>>>();      // produces dis (needed by gemm now)
    k_gemm   <<<nodeBlocks, 128>>>(x, W1); // writes h' = (xW1)*dis
    k_scatter<<<edge4Blocks, 256>>>(ei);
    k_agg1   <<<warpBlocks, 256>>>(b1, W2);
    k_agg2   <<<warpBlocks, 256>>>(b2, out);
}

// round 7
// speedup vs baseline: 1.2500x; 1.0803x over previous
#include <cuda_runtime.h>
#include <cuda_fp16.h>

#define N_NODES 100000
#define N_EDGES 3200000
#define D_FEAT  256
#define D_HID   30
#define HPAD2   16          // half2 per row: 32 halves = 64B (slot 15 = zero pad)
#define SCAN_BLOCKS 98      // ceil(100000/1024)

// ---------------- scratch (device globals; zero-initialized at load) --------
__device__ __half2 g_h2[N_NODES * HPAD2]; // 6.4 MB pre-scaled h' = (xW1)*dis, fp16
__device__ float g_dis[N_NODES];          // rsqrt(deg)
__device__ float g_z[N_NODES];            // pre-scaled z' = z*dis
__device__ int   g_cnt[N_NODES];          // in-degree histogram (zeroed by agg2 tail)
__device__ int   g_rowptr[N_NODES + 1];   // CSR row pointers (by target col)
__device__ int   g_slot[N_EDGES];         // per-edge slot within its target row
__device__ int   g_ent[N_EDGES];          // src node per CSR slot
__device__ int   g_bsums[128];            // scan block sums

// ---------------- f32x2 packed-FMA helpers (sm_100 ISA) ----------------------
__device__ __forceinline__ unsigned long long pk2(float lo, float hi) {
    unsigned long long r;
    asm("mov.b64 %0, {%1, %2};" : "=l"(r) : "f"(lo), "f"(hi));
    return r;
}
__device__ __forceinline__ void upk2(unsigned long long v, float& lo, float& hi) {
    asm("mov.b64 {%0, %1}, %2;" : "=f"(lo), "=f"(hi) : "l"(v));
}
__device__ __forceinline__ void ffma2(unsigned long long& d,
                                      unsigned long long a, unsigned long long b) {
    asm("fma.rn.f32x2 %0, %1, %2, %0;" : "+l"(d) : "l"(a), "l"(b));
}

// ---------------- histogram + slot assignment (4 edges/thread) ---------------
__global__ void k_hist(const int* __restrict__ ei) {
    int e4 = (blockIdx.x * 256 + threadIdx.x) * 4;
    if (e4 < N_EDGES) {
        int4 c = *(const int4*)&ei[N_EDGES + e4];
        int4 s = make_int4(-1, -1, -1, -1);
        if ((unsigned)c.x < (unsigned)N_NODES) s.x = atomicAdd(&g_cnt[c.x], 1);
        if ((unsigned)c.y < (unsigned)N_NODES) s.y = atomicAdd(&g_cnt[c.y], 1);
        if ((unsigned)c.z < (unsigned)N_NODES) s.z = atomicAdd(&g_cnt[c.z], 1);
        if ((unsigned)c.w < (unsigned)N_NODES) s.w = atomicAdd(&g_cnt[c.w], 1);
        *(int4*)&g_slot[e4] = s;
    }
}

// ---------------- block-level exclusive scan --------------------------------
__global__ void k_scan1() {
    __shared__ int s[1024];
    int t = threadIdx.x;
    int i = blockIdx.x * 1024 + t;
    int v = (i < N_NODES) ? g_cnt[i] : 0;
    s[t] = v;
    __syncthreads();
    #pragma unroll
    for (int off = 1; off < 1024; off <<= 1) {
        int add = (t >= off) ? s[t - off] : 0;
        __syncthreads();
        s[t] += add;
        __syncthreads();
    }
    if (i < N_NODES) g_rowptr[i] = s[t] - v;   // block-local exclusive
    if (t == 1023) g_bsums[blockIdx.x] = s[t];
}

// ---------------- scan finalize: inline bsums prefix + dis -------------------
// 256-thread blocks; each block lies within one 1024-wide scan1 block, so it
// needs a single prefix value (sum of bsums below it), computed by warp 0.
__global__ void k_scan23() {
    __shared__ int s_pre;
    int t   = threadIdx.x;
    int i   = blockIdx.x * 256 + t;
    int big = (blockIdx.x * 256) >> 10;      // constant per block
    if (t < 32) {
        int acc = 0;
        for (int j = t; j < big; j += 32) acc += g_bsums[j];
        #pragma unroll
        for (int off = 16; off > 0; off >>= 1)
            acc += __shfl_down_sync(0xFFFFFFFFu, acc, off);
        if (t == 0) s_pre = acc;
    }
    __syncthreads();
    if (i < N_NODES) {
        g_rowptr[i] += s_pre;
        g_dis[i] = rsqrtf((float)(g_cnt[i] + 1));   // deg incl. self-loop
    }
    if (i == 0) g_rowptr[N_NODES] = N_EDGES;
}

// ---------------- CSR scatter: pure writes, no atomics -----------------------
__global__ void k_scatter(const int* __restrict__ ei) {
    int e4 = (blockIdx.x * 256 + threadIdx.x) * 4;
    if (e4 < N_EDGES) {
        int4 r = *(const int4*)&ei[e4];
        int4 c = *(const int4*)&ei[N_EDGES + e4];
        int4 s = *(const int4*)&g_slot[e4];
        if (s.x >= 0 && (unsigned)r.x < (unsigned)N_NODES)
            g_ent[g_rowptr[c.x] + s.x] = r.x;
        if (s.y >= 0 && (unsigned)r.y < (unsigned)N_NODES)
            g_ent[g_rowptr[c.y] + s.y] = r.y;
        if (s.z >= 0 && (unsigned)r.z < (unsigned)N_NODES)
            g_ent[g_rowptr[c.z] + s.z] = r.z;
        if (s.w >= 0 && (unsigned)r.w < (unsigned)N_NODES)
            g_ent[g_rowptr[c.w] + s.w] = r.w;
    }
}

// ---------------- GEMM: h' = (x @ W1) * dis  (packed f32x2 FMA, fp16 out) ----
__global__ void __launch_bounds__(128) k_gemm(const float* __restrict__ x,
                                              const float* __restrict__ W1) {
    __shared__ __align__(16) float Ws[D_FEAT * 32];  // 32 KB, rows padded to 32
    __shared__ float xs[256 * 9];                    // pad 9 vs bank conflicts
    int t  = threadIdx.x;
    int n0 = blockIdx.x * 256;

    #pragma unroll
    for (int i = 0; i < 60; i++) {                   // 60*128 = 7680 = 256*30
        int flat = t + i * 128;
        Ws[(flat / 30) * 32 + (flat % 30)] = W1[flat];
    }

    unsigned long long accA[15], accB[15];           // (j, j+1) f32 pairs
    #pragma unroll
    for (int p = 0; p < 15; p++) { accA[p] = 0ull; accB[p] = 0ull; }

    for (int kc = 0; kc < 32; kc++) {                // 32 chunks of 8 k's
        __syncthreads();
        #pragma unroll
        for (int i = 0; i < 4; i++) {                // 512 float4 loads / 128 thr
            int flat4 = t + i * 128;
            int n = flat4 >> 1;
            int p = flat4 & 1;
            int gn = n0 + n;
            if (gn < N_NODES) {
                float4 v = *(const float4*)&x[gn * D_FEAT + kc * 8 + p * 4];
                float* xr = &xs[n * 9 + p * 4];
                xr[0] = v.x; xr[1] = v.y; xr[2] = v.z; xr[3] = v.w;
            }
        }
        __syncthreads();
        #pragma unroll
        for (int kk = 0; kk < 8; kk++) {
            unsigned long long xa2 = pk2(xs[t * 9 + kk], xs[t * 9 + kk]);
            unsigned long long xb2 = pk2(xs[(t + 128) * 9 + kk], xs[(t + 128) * 9 + kk]);
            const float* wr = &Ws[(kc * 8 + kk) * 32];
            #pragma unroll
            for (int p = 0; p < 7; p++) {            // 28 floats = 14 b64 lanes
                ulonglong2 wv = *(const ulonglong2*)(wr + p * 4);
                ffma2(accA[2 * p],     xa2, wv.x);
                ffma2(accA[2 * p + 1], xa2, wv.y);
                ffma2(accB[2 * p],     xb2, wv.x);
                ffma2(accB[2 * p + 1], xb2, wv.y);
            }
            unsigned long long wl = *(const unsigned long long*)(wr + 28);
            ffma2(accA[14], xa2, wl);
            ffma2(accB[14], xb2, wl);
        }
    }

    int na = n0 + t, nb = n0 + 128 + t;
    if (na < N_NODES) {
        float d = g_dis[na];
        #pragma unroll
        for (int p = 0; p < 15; p++) {
            float f0, f1; upk2(accA[p], f0, f1);
            g_h2[na * HPAD2 + p] = __floats2half2_rn(f0 * d, f1 * d);
        }   // slot 15 is the zero pad: zero-initialized, never written
    }
    if (nb < N_NODES) {
        float d = g_dis[nb];
        #pragma unroll
        for (int p = 0; p < 15; p++) {
            float f0, f1; upk2(accB[p], f0, f1);
            g_h2[nb * HPAD2 + p] = __floats2half2_rn(f0 * d, f1 * d);
        }
    }
}

// ---------------- layer-1 aggregate + relu + (·W2) fused (fp16 gather) ------
// One warp per node; 16 lanes per edge (each lane = half2 = 2 features),
// 2 edges per warp-step, unroll 4 -> 8 edges in flight. fp32 accumulation.
__global__ void __launch_bounds__(256) k_agg1(const float* __restrict__ b1,
                                              const float* __restrict__ W2) {
    int c    = blockIdx.x * 8 + (threadIdx.x >> 5);
    int lane = threadIdx.x & 31;
    int half = lane >> 4;        // 0: even edges, 1: odd edges
    int sub  = lane & 15;        // feature pair index
    float dc = g_dis[c];
    int s = g_rowptr[c];
    int e = g_rowptr[c + 1];

    float ax0 = 0.f, ay0 = 0.f, ax1 = 0.f, ay1 = 0.f;
    float ax2 = 0.f, ay2 = 0.f, ax3 = 0.f, ay3 = 0.f;

    if (half == 0) {             // self-loop h'[c], counted once
        float2 v = __half22float2(g_h2[c * HPAD2 + sub]);
        ax0 += v.x; ay0 += v.y;
    }

    int i = s;
    for (; i + 8 <= e; i += 8) {
        int r0 = g_ent[i     + half];
        int r1 = g_ent[i + 2 + half];
        int r2 = g_ent[i + 4 + half];
        int r3 = g_ent[i + 6 + half];
        float2 v0 = __half22float2(g_h2[r0 * HPAD2 + sub]);
        float2 v1 = __half22float2(g_h2[r1 * HPAD2 + sub]);
        float2 v2 = __half22float2(g_h2[r2 * HPAD2 + sub]);
        float2 v3 = __half22float2(g_h2[r3 * HPAD2 + sub]);
        ax0 += v0.x; ay0 += v0.y;
        ax1 += v1.x; ay1 += v1.y;
        ax2 += v2.x; ay2 += v2.y;
        ax3 += v3.x; ay3 += v3.y;
    }
    for (; i < e; i += 2) {
        int my = i + half;
        if (my < e) {
            float2 v = __half22float2(g_h2[g_ent[my] * HPAD2 + sub]);
            ax0 += v.x; ay0 += v.y;
        }
    }

    float AX = (ax0 + ax1) + (ax2 + ax3);
    float AY = (ay0 + ay1) + (ay2 + ay3);
    // combine odd-edge half into even half (lanes 0..15)
    AX += __shfl_down_sync(0xFFFFFFFFu, AX, 16);
    AY += __shfl_down_sync(0xFFFFFFFFu, AY, 16);

    if (half == 0) {
        float p = 0.f;
        int j = 2 * sub;
        if (j < D_HID) {
            float h0 = fmaxf(AX * dc + b1[j],     0.f);
            float h1 = fmaxf(AY * dc + b1[j + 1], 0.f);
            p = h0 * W2[j] + h1 * W2[j + 1];
        }
        #pragma unroll
        for (int off = 8; off > 0; off >>= 1)
            p += __shfl_down_sync(0x0000FFFFu, p, off);
        if (sub == 0) g_z[c] = p * dc;          // pre-scaled z' = z*dis
    }
}

// ---------------- layer-2 scalar aggregate + sigmoid + cnt reset -------------
__global__ void __launch_bounds__(256) k_agg2(const float* __restrict__ b2,
                                              float* __restrict__ out) {
    int c    = blockIdx.x * 8 + (threadIdx.x >> 5);
    int lane = threadIdx.x & 31;
    float dc = g_dis[c];
    int s = g_rowptr[c];
    int e = g_rowptr[c + 1];

    float acc = (lane == 0) ? g_z[c] : 0.f;             // self-loop z'[c]
    for (int i = s + lane; i < e; i += 32)
        acc += g_z[g_ent[i]];
    #pragma unroll
    for (int off = 16; off > 0; off >>= 1)
        acc += __shfl_down_sync(0xFFFFFFFFu, acc, off);
    if (lane == 0) {
        float v = acc * dc + b2[0];
        out[c] = 1.f / (1.f + __expf(-v));
        g_cnt[c] = 0;          // restore histogram invariant for next replay
    }
}

// ---------------- launcher ---------------------------------------------------
extern "C" void kernel_launch(void* const* d_in, const int* in_sizes, int n_in,
                              void* d_out, int out_size) {
    const float* x  = (const float*)d_in[0];
    const int*   ei = (const int*)d_in[1];     // int64 in source -> int32 (JAX x64 disabled)
    const float* W1 = (const float*)d_in[2];
    const float* b1 = (const float*)d_in[3];
    const float* W2 = (const float*)d_in[4];
    const float* b2 = (const float*)d_in[5];
    float*       out = (float*)d_out;

    const int nodeBlocks  = (N_NODES + 255) / 256;       // 391
    const int edge4Blocks = N_EDGES / 4 / 256;           // 3125 (exact)
    const int warpBlocks  = N_NODES / 8;                 // 12500 (exact)

    k_hist   <<<edge4Blocks, 256>>>(ei);
    k_scan1  <<<SCAN_BLOCKS, 1024>>>();
    k_scan23 <<<nodeBlocks, 256>>>();      // rowptr final + dis
    k_gemm   <<<nodeBlocks, 128>>>(x, W1); // writes h' = (xW1)*dis as fp16
    k_scatter<<<edge4Blocks, 256>>>(ei);
    k_agg1   <<<warpBlocks, 256>>>(b1, W2);
    k_agg2   <<<warpBlocks, 256>>>(b2, out);
}